// round 6
// baseline (speedup 1.0000x reference)
#include <cuda_runtime.h>
#include <math.h>

// Problem constants (fixed shapes per reference)
#define NFK 4096
#define NRK 8192
#define NTH 256
#define NT 4                    // r rows per thread (2 packed pairs)
#define RBLK (NTH*NT)           // 1024 r per tile
#define FCHUNK 128              // f columns per tile
#define NCH (NFK/FCHUNK)        // 32 f-chunks
#define NRB (NRK/RBLK)          // 8 r-blocks
#define NTILES (NCH*NRB)        // 256 tiles == grid size
#define EBLK 48                 // epilogue blocks: 48*256 = NRK+NFK exactly

#define EPS_CH   1e-5f
#define EPS_ACOS 1e-6f
#define PI_F     3.14159265358979323846f

// ---------------- static device scratch (allocation-free) ----------------
// Only cross-replay mutable state is g_done: monotonic, used mod EBLK
// (exactly EBLK increments per run -> exactly one finisher per run).
__device__ unsigned g_done;
__device__ uint2    g_rpartT[NRK * NCH];   // [r][cx]  : (min_u ord, max_tr ord) - 256B/r
__device__ uint2    g_fpartT[NFK * NRB];   // [f][ry]  : (min_v ord, max_tr ord) - 64B/f
__device__ float    g_psum[EBLK * 4];      // per-epilogue-block partial sums

// Order-preserving float<->uint mapping (min/max in integer domain).
__device__ __forceinline__ unsigned ford(float f) {
    unsigned u = __float_as_uint(f);
    return (u & 0x80000000u) ? ~u : (u | 0x80000000u);
}
__device__ __forceinline__ float finv(unsigned u) {
    return __uint_as_float((u & 0x80000000u) ? (u & 0x7fffffffu) : ~u);
}

// ---------------- packed f32x2 helpers ----------------
__device__ __forceinline__ unsigned long long pk2(float a, float b) {
    unsigned long long r;
    asm("mov.b64 %0, {%1, %2};" : "=l"(r) : "f"(a), "f"(b));
    return r;
}
__device__ __forceinline__ unsigned long long ffma2(unsigned long long a,
                                                    unsigned long long b,
                                                    unsigned long long c) {
    unsigned long long d;
    asm("fma.rn.f32x2 %0, %1, %2, %3;" : "=l"(d) : "l"(a), "l"(b), "l"(c));
    return d;
}
__device__ __forceinline__ unsigned long long fmul2(unsigned long long a,
                                                    unsigned long long b) {
    unsigned long long d;
    asm("mul.rn.f32x2 %0, %1, %2;" : "=l"(d) : "l"(a), "l"(b));
    return d;
}
__device__ __forceinline__ float f2lo(unsigned long long v) {
    return __uint_as_float((unsigned)v);
}
__device__ __forceinline__ float f2hi(unsigned long long v) {
    return __uint_as_float((unsigned)(v >> 32));
}

// ---------------- all-pairs kernel: one tile per block ----------------
// Shared f-tile layout: per f, 14 float2 slots (112 B), each value duplicated
// (v,v) so LDS.128 yields ready-to-use packed-broadcast operands.
__global__ __launch_bounds__(NTH, 2)
void pair_kernel(const float* __restrict__ t_fake,
                 const float* __restrict__ R_fake,
                 const float* __restrict__ r_buffer,
                 const float* __restrict__ t_buffer) {
    __shared__ __align__(16) float sf[FCHUNK * 28];          // 14 KB
    __shared__ __align__(16) uint2 s_fred[FCHUNK][8];        // 8 KB per-warp f results

    const int tid  = threadIdx.x;
    const int lane = tid & 31;
    const int warp = tid >> 5;

    const int cx = blockIdx.x & (NCH - 1);
    const int ry = blockIdx.x >> 5;
    const int fbase = cx * FCHUNK;
    const int rbase = ry * RBLK;

    // ---- stage duplicated f-tile (12 raw values per f) ----
    for (int i = tid; i < FCHUNK * 12; i += NTH) {
        int fl = i / 12, v = i - fl * 12;
        int fg = fbase + fl;
        float val = (v < 3) ? t_fake[fg * 3 + v] : R_fake[fg * 9 + (v - 3)];
        int slot = (v < 3) ? v : (v + 1);
        sf[fl * 28 + slot * 2 + 0] = val;
        sf[fl * 28 + slot * 2 + 1] = val;
    }
    for (int fl = tid; fl < FCHUNK; fl += NTH) {
        int fg = fbase + fl;
        float tx = t_fake[fg*3+0], ty = t_fake[fg*3+1], tz = t_fake[fg*3+2];
        float nf = fmaf(tx, tx, fmaf(ty, ty, tz * tz));
        sf[fl * 28 + 6] = nf;
        sf[fl * 28 + 7] = nf;
    }

    // ---- r-side registers: 4 rows as 2 packed pairs ----
    const int r0 = rbase + tid * NT;
    unsigned long long tb2[2][3], Rr2[2][9], nr2[2];
    #pragma unroll
    for (int jp = 0; jp < 2; jp++) {
        int ra = r0 + 2 * jp, rb = ra + 1;
        float ax = t_buffer[ra*3+0], ay = t_buffer[ra*3+1], az = t_buffer[ra*3+2];
        float bx = t_buffer[rb*3+0], by = t_buffer[rb*3+1], bz = t_buffer[rb*3+2];
        tb2[jp][0] = pk2(ax, bx);
        tb2[jp][1] = pk2(ay, by);
        tb2[jp][2] = pk2(az, bz);
        nr2[jp] = pk2(fmaf(ax, ax, fmaf(ay, ay, az * az)),
                      fmaf(bx, bx, fmaf(by, by, bz * bz)));
        #pragma unroll
        for (int k = 0; k < 9; k++)
            Rr2[jp][k] = pk2(r_buffer[ra*9+k], r_buffer[rb*9+k]);
    }
    __syncthreads();

    const float INF = __int_as_float(0x7f800000);
    const unsigned long long M2 = pk2(-2.0f, -2.0f);
    float minu[NT], maxtr[NT];
    #pragma unroll
    for (int j = 0; j < NT; j++) { minu[j] = INF; maxtr[j] = -INF; }

    #pragma unroll 2
    for (int f = 0; f < FCHUNK; f++) {
        const ulonglong2* fp = reinterpret_cast<const ulonglong2*>(sf + f * 28);
        ulonglong2 A = fp[0];   // tx2, ty2
        ulonglong2 B = fp[1];   // tz2, nf2
        ulonglong2 C = fp[2];   // R0, R1
        ulonglong2 D = fp[3];   // R2, R3
        ulonglong2 E = fp[4];   // R4, R5
        ulonglong2 F = fp[5];   // R6, R7
        ulonglong2 G = fp[6];   // R8, pad

        unsigned long long v2s[2], trs[2];
        #pragma unroll
        for (int jp = 0; jp < 2; jp++) {
            unsigned long long dot =
                ffma2(tb2[jp][0], A.x, ffma2(tb2[jp][1], A.y, fmul2(tb2[jp][2], B.x)));
            unsigned long long u2 = ffma2(dot, M2, B.y);       // nf - 2 dot
            v2s[jp] = ffma2(dot, M2, nr2[jp]);                 // nr - 2 dot
            unsigned long long tr = fmul2(Rr2[jp][0], C.x);
            tr = ffma2(Rr2[jp][1], C.y, tr);
            tr = ffma2(Rr2[jp][2], D.x, tr);
            tr = ffma2(Rr2[jp][3], D.y, tr);
            tr = ffma2(Rr2[jp][4], E.x, tr);
            tr = ffma2(Rr2[jp][5], E.y, tr);
            tr = ffma2(Rr2[jp][6], F.x, tr);
            tr = ffma2(Rr2[jp][7], F.y, tr);
            tr = ffma2(Rr2[jp][8], G.x, tr);
            trs[jp] = tr;

            minu[2*jp+0]  = fminf(minu[2*jp+0],  f2lo(u2));
            minu[2*jp+1]  = fminf(minu[2*jp+1],  f2hi(u2));
            maxtr[2*jp+0] = fmaxf(maxtr[2*jp+0], f2lo(tr));
            maxtr[2*jp+1] = fmaxf(maxtr[2*jp+1], f2hi(tr));
        }
        float fv = fminf(fminf(f2lo(v2s[0]), f2hi(v2s[0])),
                         fminf(f2lo(v2s[1]), f2hi(v2s[1])));
        float ft = fmaxf(fmaxf(f2lo(trs[0]), f2hi(trs[0])),
                         fmaxf(f2lo(trs[1]), f2hi(trs[1])));

        unsigned rmn = __reduce_min_sync(0xffffffffu, ford(fv));
        unsigned rmx = __reduce_max_sync(0xffffffffu, ford(ft));
        if (lane == 0) s_fred[f][warp] = make_uint2(rmn, rmx);   // STS, not STG
    }

    // ---- per-r partials: transposed, contiguous per r for the epilogue ----
    #pragma unroll
    for (int j = 0; j < NT; j++)
        g_rpartT[(r0 + j) * NCH + cx] = make_uint2(ford(minu[j]), ford(maxtr[j]));

    // ---- block combine of per-warp f results: one uint2 per (f, ry) ----
    __syncthreads();
    if (tid < FCHUNK) {
        const uint4* p = reinterpret_cast<const uint4*>(&s_fred[tid][0]);
        unsigned mn = 0xFFFFFFFFu, mx = 0u;
        #pragma unroll
        for (int k = 0; k < 4; k++) {           // 4 x LDS.128 = 8 uint2
            uint4 q = p[k];
            mn = umin(mn, umin(q.x, q.z));
            mx = umax(mx, umax(q.y, q.w));
        }
        g_fpartT[(fbase + tid) * NRB + ry] = make_uint2(mn, mx);
    }
}

// ---------------- epilogue: reduce partials, sqrt/acos, fixed-order sum ----------------
// Grid is exactly (NRK+NFK)/NTH = 48 blocks; gid < NRK -> r item, else f item.
__global__ __launch_bounds__(NTH, 4)
void epilogue_kernel(const float* __restrict__ t_fake,
                     const float* __restrict__ t_buffer,
                     float* __restrict__ out) {
    const int tid = threadIdx.x;
    const int gid = blockIdx.x * NTH + tid;    // 0 .. NRK+NFK-1

    float sAngR = 0.f, sSqR = 0.f, sAngF = 0.f, sSqF = 0.f;

    if (gid < NRK) {
        // one r per thread: 256B contiguous -> 16 x LDG.128, MLP 16
        const uint4* p = reinterpret_cast<const uint4*>(&g_rpartT[gid * NCH]);
        unsigned mn = 0xFFFFFFFFu, mx = 0u;
        #pragma unroll
        for (int k = 0; k < 16; k++) {
            uint4 q = p[k];
            mn = umin(mn, umin(q.x, q.z));
            mx = umax(mx, umax(q.y, q.w));
        }
        float tx = t_buffer[gid*3+0], ty = t_buffer[gid*3+1], tz = t_buffer[gid*3+2];
        float nr = fmaf(tx, tx, fmaf(ty, ty, tz * tz));
        float td = fmaxf(nr + finv(mn), 0.0f);
        sSqR = sqrtf(td + EPS_CH);
        float cs = 0.5f * (finv(mx) - 1.0f);
        cs = fminf(fmaxf(cs, -1.0f + EPS_ACOS), 1.0f - EPS_ACOS);
        sAngR = acosf(cs);
    } else {
        // one f per thread: 64B contiguous -> 4 x LDG.128
        const int f = gid - NRK;
        const uint4* p = reinterpret_cast<const uint4*>(&g_fpartT[f * NRB]);
        unsigned mn = 0xFFFFFFFFu, mx = 0u;
        #pragma unroll
        for (int k = 0; k < 4; k++) {
            uint4 q = p[k];
            mn = umin(mn, umin(q.x, q.z));
            mx = umax(mx, umax(q.y, q.w));
        }
        float tx = t_fake[f*3+0], ty = t_fake[f*3+1], tz = t_fake[f*3+2];
        float nf = fmaf(tx, tx, fmaf(ty, ty, tz * tz));
        float td = fmaxf(nf + finv(mn), 0.0f);
        sSqF = sqrtf(td + EPS_CH);
        float cs = 0.5f * (finv(mx) - 1.0f);
        cs = fminf(fmaxf(cs, -1.0f + EPS_ACOS), 1.0f - EPS_ACOS);
        sAngF = acosf(cs);
    }

    // fixed-tree block reduction (deterministic)
    #pragma unroll
    for (int off = 16; off; off >>= 1) {
        sAngR += __shfl_xor_sync(0xffffffffu, sAngR, off);
        sSqR  += __shfl_xor_sync(0xffffffffu, sSqR,  off);
        sAngF += __shfl_xor_sync(0xffffffffu, sAngF, off);
        sSqF  += __shfl_xor_sync(0xffffffffu, sSqF,  off);
    }
    __shared__ float buf[NTH/32][4];
    int w = tid >> 5, l = tid & 31;
    if (l == 0) { buf[w][0] = sAngR; buf[w][1] = sSqR; buf[w][2] = sAngF; buf[w][3] = sSqF; }
    __syncthreads();

    if (tid == 0) {
        float a0 = 0.f, a1 = 0.f, a2 = 0.f, a3 = 0.f;
        #pragma unroll
        for (int i = 0; i < NTH/32; i++) {
            a0 += buf[i][0]; a1 += buf[i][1]; a2 += buf[i][2]; a3 += buf[i][3];
        }
        g_psum[blockIdx.x*4+0] = a0;
        g_psum[blockIdx.x*4+1] = a1;
        g_psum[blockIdx.x*4+2] = a2;
        g_psum[blockIdx.x*4+3] = a3;

        __threadfence();
        unsigned old = atomicAdd(&g_done, 1u);
        if ((old % EBLK) == (EBLK - 1)) {
            // exactly one finisher per run: fixed-order final combine
            __threadfence();
            float c0 = 0.f, c1 = 0.f, c2 = 0.f, c3 = 0.f;
            for (int i = 0; i < EBLK; i++) {
                c0 += g_psum[i*4+0]; c1 += g_psum[i*4+1];
                c2 += g_psum[i*4+2]; c3 += g_psum[i*4+3];
            }
            float rloss = c2 / (float)NFK + c0 / (float)NRK;
            float tloss = c1 / (float)NRK + c3 / (float)NFK;
            out[0] = rloss + tloss * PI_F;
        }
    }
}

// ---------------- launch ----------------
extern "C" void kernel_launch(void* const* d_in, const int* in_sizes, int n_in,
                              void* d_out, int out_size) {
    const float* t_fake   = nullptr;  // 4096*3
    const float* R_fake   = nullptr;  // 4096*9
    const float* r_buffer = nullptr;  // 8192*9
    const float* t_buffer = nullptr;  // 8192*3
    for (int i = 0; i < n_in; i++) {
        switch (in_sizes[i]) {
            case NFK*3: t_fake   = (const float*)d_in[i]; break;
            case NFK*9: R_fake   = (const float*)d_in[i]; break;
            case NRK*9: r_buffer = (const float*)d_in[i]; break;
            case NRK*3: t_buffer = (const float*)d_in[i]; break;
            default: break;
        }
    }

    pair_kernel<<<NTILES, NTH>>>(t_fake, R_fake, r_buffer, t_buffer);
    epilogue_kernel<<<EBLK, NTH>>>(t_fake, t_buffer, (float*)d_out);
}

// round 7
// speedup vs baseline: 1.0629x; 1.0629x over previous
#include <cuda_runtime.h>
#include <math.h>

// Problem constants (fixed shapes per reference)
#define NFK 4096
#define NRK 8192
#define NTH 256
#define NT 4                    // r rows per thread (2 packed pairs)
#define RBLK (NTH*NT)           // 1024 r per tile
#define FCHUNK 128              // f columns per tile
#define NCH (NFK/FCHUNK)        // 32 f-chunks
#define NRB (NRK/RBLK)          // 8 r-blocks
#define NTILES (NCH*NRB)        // 256 tiles == grid size
#define EBLK 48                 // epilogue blocks: 48*256 = NRK+NFK exactly

#define EPS_CH   1e-5f
#define EPS_ACOS 1e-6f
#define PI_F     3.14159265358979323846f

// ---------------- static device scratch (allocation-free) ----------------
// ALL scratch words have reset value 0 ("no update"): zero-initialized for the
// first run, and the epilogue writes 0 back after reading each word, restoring
// the invariant for the next graph replay. Encodings are chosen so every real
// update is > 0 and the combine is always atomicMax (order-independent).
__device__ unsigned g_done;           // monotonic, used mod EBLK
__device__ unsigned g_ru[NRK];        // max of ~ford(u)  -> min over f of u
__device__ unsigned g_rtr[NRK];       // max of  ford(tr) -> max over f of tr
__device__ unsigned g_fv[NFK];        // max of ~ford(v)  -> min over r of v
__device__ unsigned g_ftr[NFK];       // max of  ford(tr) -> max over r of tr
__device__ float    g_psum[EBLK * 4]; // per-epilogue-block partial sums

// Order-preserving float<->uint mapping (min/max in integer domain).
// For finite x: 0 < ford(x) < 0xFFFFFFFF, so both ford and ~ford are > 0.
__device__ __forceinline__ unsigned ford(float f) {
    unsigned u = __float_as_uint(f);
    return (u & 0x80000000u) ? ~u : (u | 0x80000000u);
}
__device__ __forceinline__ float finv(unsigned u) {
    return __uint_as_float((u & 0x80000000u) ? (u & 0x7fffffffu) : ~u);
}

// ---------------- packed f32x2 helpers ----------------
__device__ __forceinline__ unsigned long long pk2(float a, float b) {
    unsigned long long r;
    asm("mov.b64 %0, {%1, %2};" : "=l"(r) : "f"(a), "f"(b));
    return r;
}
__device__ __forceinline__ unsigned long long ffma2(unsigned long long a,
                                                    unsigned long long b,
                                                    unsigned long long c) {
    unsigned long long d;
    asm("fma.rn.f32x2 %0, %1, %2, %3;" : "=l"(d) : "l"(a), "l"(b), "l"(c));
    return d;
}
__device__ __forceinline__ unsigned long long fmul2(unsigned long long a,
                                                    unsigned long long b) {
    unsigned long long d;
    asm("mul.rn.f32x2 %0, %1, %2;" : "=l"(d) : "l"(a), "l"(b));
    return d;
}
__device__ __forceinline__ float f2lo(unsigned long long v) {
    return __uint_as_float((unsigned)v);
}
__device__ __forceinline__ float f2hi(unsigned long long v) {
    return __uint_as_float((unsigned)(v >> 32));
}

// ---------------- all-pairs kernel: one tile per block ----------------
// Shared f-tile layout: per f, 14 float2 slots (112 B), each value duplicated
// (v,v) so LDS.128 yields ready-to-use packed-broadcast operands.
__global__ __launch_bounds__(NTH, 2)
void pair_kernel(const float* __restrict__ t_fake,
                 const float* __restrict__ R_fake,
                 const float* __restrict__ r_buffer,
                 const float* __restrict__ t_buffer) {
    __shared__ __align__(16) float sf[FCHUNK * 28];          // 14 KB
    __shared__ __align__(16) uint2 s_fred[FCHUNK][8];        // 8 KB per-warp f results

    const int tid  = threadIdx.x;
    const int lane = tid & 31;
    const int warp = tid >> 5;

    const int cx = blockIdx.x & (NCH - 1);
    const int ry = blockIdx.x >> 5;
    const int fbase = cx * FCHUNK;
    const int rbase = ry * RBLK;

    // ---- stage duplicated f-tile (12 raw values per f) ----
    for (int i = tid; i < FCHUNK * 12; i += NTH) {
        int fl = i / 12, v = i - fl * 12;
        int fg = fbase + fl;
        float val = (v < 3) ? t_fake[fg * 3 + v] : R_fake[fg * 9 + (v - 3)];
        int slot = (v < 3) ? v : (v + 1);
        sf[fl * 28 + slot * 2 + 0] = val;
        sf[fl * 28 + slot * 2 + 1] = val;
    }
    for (int fl = tid; fl < FCHUNK; fl += NTH) {
        int fg = fbase + fl;
        float tx = t_fake[fg*3+0], ty = t_fake[fg*3+1], tz = t_fake[fg*3+2];
        float nf = fmaf(tx, tx, fmaf(ty, ty, tz * tz));
        sf[fl * 28 + 6] = nf;
        sf[fl * 28 + 7] = nf;
    }

    // ---- r-side registers: 4 rows as 2 packed pairs ----
    const int r0 = rbase + tid * NT;
    unsigned long long tb2[2][3], Rr2[2][9], nr2[2];
    #pragma unroll
    for (int jp = 0; jp < 2; jp++) {
        int ra = r0 + 2 * jp, rb = ra + 1;
        float ax = t_buffer[ra*3+0], ay = t_buffer[ra*3+1], az = t_buffer[ra*3+2];
        float bx = t_buffer[rb*3+0], by = t_buffer[rb*3+1], bz = t_buffer[rb*3+2];
        tb2[jp][0] = pk2(ax, bx);
        tb2[jp][1] = pk2(ay, by);
        tb2[jp][2] = pk2(az, bz);
        nr2[jp] = pk2(fmaf(ax, ax, fmaf(ay, ay, az * az)),
                      fmaf(bx, bx, fmaf(by, by, bz * bz)));
        #pragma unroll
        for (int k = 0; k < 9; k++)
            Rr2[jp][k] = pk2(r_buffer[ra*9+k], r_buffer[rb*9+k]);
    }
    __syncthreads();

    const float INF = __int_as_float(0x7f800000);
    const unsigned long long M2 = pk2(-2.0f, -2.0f);
    float minu[NT], maxtr[NT];
    #pragma unroll
    for (int j = 0; j < NT; j++) { minu[j] = INF; maxtr[j] = -INF; }

    #pragma unroll 2
    for (int f = 0; f < FCHUNK; f++) {
        const ulonglong2* fp = reinterpret_cast<const ulonglong2*>(sf + f * 28);
        ulonglong2 A = fp[0];   // tx2, ty2
        ulonglong2 B = fp[1];   // tz2, nf2
        ulonglong2 C = fp[2];   // R0, R1
        ulonglong2 D = fp[3];   // R2, R3
        ulonglong2 E = fp[4];   // R4, R5
        ulonglong2 F = fp[5];   // R6, R7
        ulonglong2 G = fp[6];   // R8, pad

        unsigned long long v2s[2], trs[2];
        #pragma unroll
        for (int jp = 0; jp < 2; jp++) {
            unsigned long long dot =
                ffma2(tb2[jp][0], A.x, ffma2(tb2[jp][1], A.y, fmul2(tb2[jp][2], B.x)));
            unsigned long long u2 = ffma2(dot, M2, B.y);       // nf - 2 dot
            v2s[jp] = ffma2(dot, M2, nr2[jp]);                 // nr - 2 dot
            unsigned long long tr = fmul2(Rr2[jp][0], C.x);
            tr = ffma2(Rr2[jp][1], C.y, tr);
            tr = ffma2(Rr2[jp][2], D.x, tr);
            tr = ffma2(Rr2[jp][3], D.y, tr);
            tr = ffma2(Rr2[jp][4], E.x, tr);
            tr = ffma2(Rr2[jp][5], E.y, tr);
            tr = ffma2(Rr2[jp][6], F.x, tr);
            tr = ffma2(Rr2[jp][7], F.y, tr);
            tr = ffma2(Rr2[jp][8], G.x, tr);
            trs[jp] = tr;

            minu[2*jp+0]  = fminf(minu[2*jp+0],  f2lo(u2));
            minu[2*jp+1]  = fminf(minu[2*jp+1],  f2hi(u2));
            maxtr[2*jp+0] = fmaxf(maxtr[2*jp+0], f2lo(tr));
            maxtr[2*jp+1] = fmaxf(maxtr[2*jp+1], f2hi(tr));
        }
        float fv = fminf(fminf(f2lo(v2s[0]), f2hi(v2s[0])),
                         fminf(f2lo(v2s[1]), f2hi(v2s[1])));
        float ft = fmaxf(fmaxf(f2lo(trs[0]), f2hi(trs[0])),
                         fmaxf(f2lo(trs[1]), f2hi(trs[1])));

        // inverted-min encoding: both reductions are MAX, reset value 0
        unsigned ev = __reduce_max_sync(0xffffffffu, ~ford(fv));
        unsigned et = __reduce_max_sync(0xffffffffu, ford(ft));
        if (lane == 0) s_fred[f][warp] = make_uint2(ev, et);   // STS, not STG
    }

    // ---- per-r merge: fire-and-forget RED.MAX into 12K-word scratch ----
    #pragma unroll
    for (int j = 0; j < NT; j++) {
        atomicMax(&g_ru[r0 + j],  ~ford(minu[j]));
        atomicMax(&g_rtr[r0 + j],  ford(maxtr[j]));
    }

    // ---- block combine of per-warp f results, then RED.MAX (2 per f) ----
    __syncthreads();
    if (tid < FCHUNK) {
        const uint4* p = reinterpret_cast<const uint4*>(&s_fred[tid][0]);
        unsigned ev = 0u, et = 0u;
        #pragma unroll
        for (int k = 0; k < 4; k++) {           // 4 x LDS.128 = 8 uint2
            uint4 q = p[k];
            ev = umax(ev, umax(q.x, q.z));
            et = umax(et, umax(q.y, q.w));
        }
        atomicMax(&g_fv[fbase + tid],  ev);
        atomicMax(&g_ftr[fbase + tid], et);
    }
}

// ---------------- epilogue: 96KB read, sqrt/acos, fixed-order sum ----------------
// Grid is exactly (NRK+NFK)/NTH = 48 blocks; gid < NRK -> r item, else f item.
// Each thread reads its scratch words once and writes 0 back (re-arms replay).
__global__ __launch_bounds__(NTH, 4)
void epilogue_kernel(const float* __restrict__ t_fake,
                     const float* __restrict__ t_buffer,
                     float* __restrict__ out) {
    const int tid = threadIdx.x;
    const int gid = blockIdx.x * NTH + tid;    // 0 .. NRK+NFK-1

    float sAngR = 0.f, sSqR = 0.f, sAngF = 0.f, sSqF = 0.f;

    if (gid < NRK) {
        unsigned eu = g_ru[gid];
        unsigned et = g_rtr[gid];
        g_ru[gid] = 0u;
        g_rtr[gid] = 0u;
        float mu = finv(~eu);                  // decode inverted-min
        float tr = finv(et);
        float tx = t_buffer[gid*3+0], ty = t_buffer[gid*3+1], tz = t_buffer[gid*3+2];
        float nr = fmaf(tx, tx, fmaf(ty, ty, tz * tz));
        float td = fmaxf(nr + mu, 0.0f);
        sSqR = sqrtf(td + EPS_CH);
        float cs = 0.5f * (tr - 1.0f);
        cs = fminf(fmaxf(cs, -1.0f + EPS_ACOS), 1.0f - EPS_ACOS);
        sAngR = acosf(cs);
    } else {
        const int f = gid - NRK;
        unsigned ev = g_fv[f];
        unsigned et = g_ftr[f];
        g_fv[f] = 0u;
        g_ftr[f] = 0u;
        float mv = finv(~ev);
        float tr = finv(et);
        float tx = t_fake[f*3+0], ty = t_fake[f*3+1], tz = t_fake[f*3+2];
        float nf = fmaf(tx, tx, fmaf(ty, ty, tz * tz));
        float td = fmaxf(nf + mv, 0.0f);
        sSqF = sqrtf(td + EPS_CH);
        float cs = 0.5f * (tr - 1.0f);
        cs = fminf(fmaxf(cs, -1.0f + EPS_ACOS), 1.0f - EPS_ACOS);
        sAngF = acosf(cs);
    }

    // fixed-tree block reduction (deterministic)
    #pragma unroll
    for (int off = 16; off; off >>= 1) {
        sAngR += __shfl_xor_sync(0xffffffffu, sAngR, off);
        sSqR  += __shfl_xor_sync(0xffffffffu, sSqR,  off);
        sAngF += __shfl_xor_sync(0xffffffffu, sAngF, off);
        sSqF  += __shfl_xor_sync(0xffffffffu, sSqF,  off);
    }
    __shared__ float buf[NTH/32][4];
    int w = tid >> 5, l = tid & 31;
    if (l == 0) { buf[w][0] = sAngR; buf[w][1] = sSqR; buf[w][2] = sAngF; buf[w][3] = sSqF; }
    __syncthreads();

    if (tid == 0) {
        float a0 = 0.f, a1 = 0.f, a2 = 0.f, a3 = 0.f;
        #pragma unroll
        for (int i = 0; i < NTH/32; i++) {
            a0 += buf[i][0]; a1 += buf[i][1]; a2 += buf[i][2]; a3 += buf[i][3];
        }
        g_psum[blockIdx.x*4+0] = a0;
        g_psum[blockIdx.x*4+1] = a1;
        g_psum[blockIdx.x*4+2] = a2;
        g_psum[blockIdx.x*4+3] = a3;

        __threadfence();
        unsigned old = atomicAdd(&g_done, 1u);
        if ((old % EBLK) == (EBLK - 1)) {
            // exactly one finisher per run: fixed-order final combine
            __threadfence();
            float c0 = 0.f, c1 = 0.f, c2 = 0.f, c3 = 0.f;
            for (int i = 0; i < EBLK; i++) {
                c0 += g_psum[i*4+0]; c1 += g_psum[i*4+1];
                c2 += g_psum[i*4+2]; c3 += g_psum[i*4+3];
            }
            float rloss = c2 / (float)NFK + c0 / (float)NRK;
            float tloss = c1 / (float)NRK + c3 / (float)NFK;
            out[0] = rloss + tloss * PI_F;
        }
    }
}

// ---------------- launch ----------------
extern "C" void kernel_launch(void* const* d_in, const int* in_sizes, int n_in,
                              void* d_out, int out_size) {
    const float* t_fake   = nullptr;  // 4096*3
    const float* R_fake   = nullptr;  // 4096*9
    const float* r_buffer = nullptr;  // 8192*9
    const float* t_buffer = nullptr;  // 8192*3
    for (int i = 0; i < n_in; i++) {
        switch (in_sizes[i]) {
            case NFK*3: t_fake   = (const float*)d_in[i]; break;
            case NFK*9: R_fake   = (const float*)d_in[i]; break;
            case NRK*9: r_buffer = (const float*)d_in[i]; break;
            case NRK*3: t_buffer = (const float*)d_in[i]; break;
            default: break;
        }
    }

    pair_kernel<<<NTILES, NTH>>>(t_fake, R_fake, r_buffer, t_buffer);
    epilogue_kernel<<<EBLK, NTH>>>(t_fake, t_buffer, (float*)d_out);
}